// round 1
// baseline (speedup 1.0000x reference)
#include <cuda_runtime.h>
#include <cstdint>

#define RNODES 256
#define LUTWORDS 8192        // 2^18 bits / 32
#define MSAMP 512
#define SSTEPS 512
#define NIN 32               // D*B
#define NOUT 10

// Persistent scratch (device globals — no runtime allocation allowed)
__device__ unsigned g_lutpk[RNODES * LUTWORDS];   // 8 MB bit-packed LUT
__device__ unsigned g_xbits[MSAMP * SSTEPS];      // 1 MB: 32 input bits per (m,t)
__device__ unsigned g_Wlo[64 * RNODES];           // chunk-major low bytes of primes*W
__device__ unsigned g_hib[24 * RNODES];           // [b(0..2)][w(0..7)][j] hi bitplanes
__device__ int g_is_u8;                           // bool serialization flag

// ---------------------------------------------------------------------------
// Detect whether bool tensors are serialized as 1-byte or 4-byte elements.
// If int32-encoded, every byte at offset % 4 != 0 is zero. Random 0/1 data in
// u8 encoding makes a false negative astronomically unlikely.
// ---------------------------------------------------------------------------
__global__ void k_detect(const void* xraw) {
    const unsigned char* p = (const unsigned char*)xraw;
    int t = threadIdx.x;
    int found = 0;
    for (int i = t; i < 4096; i += 256)
        if ((i & 3) && p[i]) found = 1;
    found = __syncthreads_or(found);
    if (t == 0) g_is_u8 = found ? 1 : 0;
}

// ---------------------------------------------------------------------------
// Pack the 256MB int32 0/1 LUT into 8MB of bits (fully coalesced, ballot).
// ---------------------------------------------------------------------------
__global__ void k_lutpack(const int* __restrict__ lut) {
    unsigned g = blockIdx.x * 256u + threadIdx.x;      // over 67,108,864
    unsigned v = (unsigned)lut[g] & 1u;
    unsigned m = __ballot_sync(0xffffffffu, v);
    if ((threadIdx.x & 31u) == 0u) g_lutpk[g >> 5] = m;
}

// ---------------------------------------------------------------------------
// Pack x[m, t, :] (32 bools) into one u32 per (m,t).
// ---------------------------------------------------------------------------
__global__ void k_xpack(const void* xraw) {
    unsigned g = blockIdx.x * 256u + threadIdx.x;      // over 8,388,608
    unsigned v;
    if (g_is_u8) v = ((const unsigned char*)xraw)[g] & 1u;
    else         v = (unsigned)((const int*)xraw)[g] & 1u;
    unsigned m = __ballot_sync(0xffffffffu, v);
    if ((threadIdx.x & 31u) == 0u) g_xbits[g >> 5] = m;
}

// ---------------------------------------------------------------------------
// Build weight structures. Wp[j,k] = W[j,k] ? primes[k] : 0, split as
//   lo = Wp & 255  -> chunk-major u32 (4 bytes of k per word) for dp4a
//   hi = Wp >> 8 (0..6) -> 3 bitplanes over k, 8 words of 32 bits each
// Thread t handles (j = t>>3, w = t&7), i.e. k in [32w, 32w+32).
// ---------------------------------------------------------------------------
__global__ void k_wprep(const void* wraw, const int* __restrict__ primes) {
    int t = blockIdx.x * 256 + threadIdx.x;            // 0..2047
    if (t >= RNODES * 8) return;
    int j = t >> 3, w = t & 7;
    unsigned lo[8] = {0, 0, 0, 0, 0, 0, 0, 0};
    unsigned hb0 = 0, hb1 = 0, hb2 = 0;
    int flag = g_is_u8;
    for (int kk = 0; kk < 32; kk++) {
        int k = w * 32 + kk;
        unsigned wv = flag ? (unsigned)(((const unsigned char*)wraw)[j * RNODES + k] & 1)
                           : ((unsigned)((const int*)wraw)[j * RNODES + k] & 1u);
        unsigned p = wv ? (unsigned)primes[k] : 0u;
        lo[kk >> 2] |= (p & 255u) << ((kk & 3) * 8);
        unsigned h = p >> 8;
        hb0 |= (h & 1u) << kk;
        hb1 |= ((h >> 1) & 1u) << kk;
        hb2 |= ((h >> 2) & 1u) << kk;
    }
    for (int cc = 0; cc < 8; cc++)
        g_Wlo[(w * 8 + cc) * RNODES + j] = lo[cc];
    g_hib[(0 * 8 + w) * RNODES + j] = hb0;
    g_hib[(1 * 8 + w) * RNODES + j] = hb1;
    g_hib[(2 * 8 + w) * RNODES + j] = hb2;
}

// ---------------------------------------------------------------------------
// Main reservoir kernel: 1 CTA per sample, thread j = node j.
// ---------------------------------------------------------------------------
__global__ void __launch_bounds__(256, 2)
k_main(const int* __restrict__ input_nodes,
       const void* __restrict__ initraw,
       const float* __restrict__ rW,
       const float* __restrict__ rb,
       float* __restrict__ out)
{
    __shared__ unsigned s_x[SSTEPS];                   // 2 KB
    __shared__ unsigned char s_rbytes[2][RNODES];      // double-buffered r (bytes)
    __shared__ unsigned s_rbits[2][8];                 // double-buffered r (bits)

    const int m = blockIdx.x;
    const int j = threadIdx.x;
    const int lane = j & 31, warp = j >> 5;

    // stage this sample's packed inputs
    for (int i = j; i < SSTEPS; i += 256) s_x[i] = g_xbits[m * SSTEPS + i];

    // weights into registers (static across all 512 steps)
    unsigned Wlo[64];
#pragma unroll
    for (int c = 0; c < 64; c++) Wlo[c] = g_Wlo[c * RNODES + j];
    unsigned HB0[8], HB1[8], HB2[8];
#pragma unroll
    for (int w = 0; w < 8; w++) {
        HB0[w] = g_hib[(0 * 8 + w) * RNODES + j];
        HB1[w] = g_hib[(1 * 8 + w) * RNODES + j];
        HB2[w] = g_hib[(2 * 8 + w) * RNODES + j];
    }

    // is this node an input node, and which bit does it take?
    int isin = 0, ipos = 0;
    for (int i = 0; i < NIN; i++) {
        int n = input_nodes[i];
        if (n == j) { isin = 1; ipos = i; }
    }

    const int flag = g_is_u8;
    unsigned myr = flag ? (unsigned)(((const unsigned char*)initraw)[j] & 1)
                        : ((unsigned)((const int*)initraw)[j] & 1u);

    const unsigned* lutp = g_lutpk + ((unsigned)j << 13);

    __syncthreads();   // s_x visible before loop

    int buf = 0;
    for (int t = 0; t < SSTEPS; t++) {
        // (a) input overwrite
        unsigned xw = s_x[t];
        if (isin) myr = (xw >> ipos) & 1u;

        // publish r (bytes for dp4a, bits for hi popcount)
        unsigned wb = __ballot_sync(0xffffffffu, myr);
        s_rbytes[buf][j] = (unsigned char)myr;
        if (lane == 0) s_rbits[buf][warp] = wb;
        __syncthreads();

        // (b) idx = lo-dot (dp4a) + (hi-dot << 8) (bitplane popcount)
        const unsigned* r4 = (const unsigned*)s_rbytes[buf];
        unsigned a0 = 0, a1 = 0, a2 = 0, a3 = 0;
#pragma unroll
        for (int c = 0; c < 64; c += 4) {
            a0 = __dp4a(r4[c + 0], Wlo[c + 0], a0);
            a1 = __dp4a(r4[c + 1], Wlo[c + 1], a1);
            a2 = __dp4a(r4[c + 2], Wlo[c + 2], a2);
            a3 = __dp4a(r4[c + 3], Wlo[c + 3], a3);
        }
        unsigned h0 = 0, h1 = 0, h2 = 0;
#pragma unroll
        for (int w = 0; w < 8; w++) {
            unsigned rbw = s_rbits[buf][w];
            h0 += __popc(rbw & HB0[w]);
            h1 += __popc(rbw & HB1[w]);
            h2 += __popc(rbw & HB2[w]);
        }
        unsigned idx = (a0 + a1) + (a2 + a3) + ((h0 + 2u * h1 + 4u * h2) << 8);

        // (c) LUT bit lookup (L2-resident packed table)
        unsigned wv = __ldg(lutp + (idx >> 5));
        myr = (wv >> (idx & 31u)) & 1u;

        buf ^= 1;
    }

    // readout: out[m, o] = sum_j rW[o, j] * rf[j] + rb[o]
    s_rbytes[buf][j] = (unsigned char)myr;
    __syncthreads();
    if (j < NOUT) {
        float acc = rb[j];
        const float* wr = rW + j * RNODES;
        for (int k = 0; k < RNODES; k++)
            acc += wr[k] * (float)s_rbytes[buf][k];
        out[m * NOUT + j] = acc;
    }
}

// ---------------------------------------------------------------------------
// d_in order: x, input_nodes, lut, W_res, primes, init_res, readout_W, readout_b
// ---------------------------------------------------------------------------
extern "C" void kernel_launch(void* const* d_in, const int* in_sizes, int n_in,
                              void* d_out, int out_size) {
    (void)in_sizes; (void)n_in; (void)out_size;
    const void*  x       = d_in[0];
    const int*   innodes = (const int*)d_in[1];
    const int*   lut     = (const int*)d_in[2];
    const void*  wres    = d_in[3];
    const int*   primes  = (const int*)d_in[4];
    const void*  initres = d_in[5];
    const float* rW      = (const float*)d_in[6];
    const float* rb      = (const float*)d_in[7];
    float* out = (float*)d_out;

    k_detect<<<1, 256>>>(x);
    k_lutpack<<<(RNODES * LUTWORDS * 32) / 256, 256>>>(lut);   // 262144 blocks
    k_xpack<<<(MSAMP * SSTEPS * 32) / 256, 256>>>(x);          // 32768 blocks
    k_wprep<<<8, 256>>>(wres, primes);
    k_main<<<MSAMP, 256>>>(innodes, initres, rW, rb, out);
}